// round 4
// baseline (speedup 1.0000x reference)
#include <cuda_runtime.h>
#include <math.h>

#define WPB 12            // warps per block
#define PPW 8             // points per warp
#define NTHREADS (WPB*32)
#define WPAD 68           // padded row stride (floats) -> conflict-free LDS.128

// fixed problem geometry
#define C_STRIDE 2097152ULL     // 256*256*32
#define B_STRIDE 67108864ULL    // 32*256*256*32
#define I_STRIDE 8192           // 256*32
#define J_STRIDE 32

struct __align__(16) Smem {
  float Wzh[64][WPAD], Wrh[64][WPAD], Wqh[64][WPAD];   // h-parts (cols 0..63)
  float Wzx[64][WPAD], Wrx[64][WPAD], Wqx[64][WPAD];   // x-parts (cols 64..127)
  float Wd1h[32][WPAD], Wd1x[32][WPAD];
  float bz[64], br[64], bq[64], bd1[32];
  float Wd2[3][32];
  float bd2[4];
  float h[WPB*PPW][64];   // per-point hidden state
  float g[WPB*PPW][64];   // scratch: x during precompute, r*h during iters, hmid at end
};

__device__ __forceinline__ float fast_sigmoid(float x) {
  return __fdividef(1.0f, 1.0f + __expf(-x));
}
__device__ __forceinline__ float fast_tanh(float x) {
  return __fdividef(2.0f, 1.0f + __expf(-2.0f * x)) - 1.0f;
}

// ---- packed f32x2 helpers ----
__device__ __forceinline__ void fma2(unsigned long long& acc,
                                     unsigned long long a, unsigned long long b) {
  asm("fma.rn.f32x2 %0, %1, %2, %0;" : "+l"(acc) : "l"(a), "l"(b));
}
__device__ __forceinline__ unsigned long long pack2(float lo, float hi) {
  unsigned long long r;
  asm("mov.b64 %0, {%1, %2};" : "=l"(r) : "f"(lo), "f"(hi));
  return r;
}
__device__ __forceinline__ float unpack_sum(unsigned long long v) {
  float lo, hi;
  asm("mov.b64 {%0, %1}, %2;" : "=f"(lo), "=f"(hi) : "l"(v));
  return lo + hi;
}
__device__ __forceinline__ ulonglong2 ld2(const float* p) {
  return *reinterpret_cast<const ulonglong2*>(p);
}

__global__ __launch_bounds__(NTHREADS, 1)
void gru_decoder_kernel(
    const float* __restrict__ before, const float* __restrict__ after,
    const float* __restrict__ pf, const int* __restrict__ coords,
    const float* __restrict__ Wz, const float* __restrict__ bz,
    const float* __restrict__ Wr, const float* __restrict__ br,
    const float* __restrict__ Wq, const float* __restrict__ bq,
    const float* __restrict__ Wd1, const float* __restrict__ bd1,
    const float* __restrict__ Wd2, const float* __restrict__ bd2,
    float* __restrict__ out, int N, int total_pts)
{
  extern __shared__ char smem_raw[];
  Smem& s = *reinterpret_cast<Smem*>(smem_raw);

  const int tid = threadIdx.x;

  // ---- load + split weights into shared (once per block) ----
  for (int idx = tid; idx < 64 * 64; idx += NTHREADS) {
    int t = idx >> 6, k = idx & 63;
    s.Wzh[t][k] = Wz[t * 128 + k];      s.Wzx[t][k] = Wz[t * 128 + 64 + k];
    s.Wrh[t][k] = Wr[t * 128 + k];      s.Wrx[t][k] = Wr[t * 128 + 64 + k];
    s.Wqh[t][k] = Wq[t * 128 + k];      s.Wqx[t][k] = Wq[t * 128 + 64 + k];
  }
  for (int idx = tid; idx < 32 * 64; idx += NTHREADS) {
    int t = idx >> 6, k = idx & 63;
    s.Wd1h[t][k] = Wd1[t * 128 + k];    s.Wd1x[t][k] = Wd1[t * 128 + 64 + k];
  }
  if (tid < 64) { s.bz[tid] = bz[tid]; s.br[tid] = br[tid]; s.bq[tid] = bq[tid]; }
  if (tid < 32) s.bd1[tid] = bd1[tid];
  if (tid < 96) ((float*)s.Wd2)[tid] = Wd2[tid];
  if (tid < 3)  s.bd2[tid] = bd2[tid];
  __syncthreads();

  const int warp = tid >> 5, lane = tid & 31;
  const int P0 = warp * PPW;
  const int nchunks = (total_pts + PPW - 1) / PPW;
  const int gwarps = gridDim.x * WPB;

  // one packed matvec pass: acc(lane out, lane+32 out) over 64-dim vec in smem
  // (defined inline below via macro to keep reg pressure per pass bounded)
#define MV_PASS(W0, VECBASE, INIT0, INIT1, OUT0, OUT1)                        \
  {                                                                           \
    unsigned long long acc0[PPW], acc1[PPW];                                  \
    _Pragma("unroll")                                                         \
    for (int p = 0; p < PPW; p++) {                                           \
      acc0[p] = pack2(INIT0, 0.0f);                                           \
      acc1[p] = pack2(INIT1, 0.0f);                                           \
    }                                                                         \
    _Pragma("unroll 4")                                                       \
    for (int k4 = 0; k4 < 16; k4++) {                                         \
      ulonglong2 w0 = ld2(&s.W0[lane][k4 * 4]);                               \
      ulonglong2 w1 = ld2(&s.W0[lane + 32][k4 * 4]);                          \
      _Pragma("unroll")                                                       \
      for (int p = 0; p < PPW; p++) {                                         \
        ulonglong2 vv = ld2(&s.VECBASE[P0 + p][k4 * 4]);                      \
        fma2(acc0[p], w0.x, vv.x); fma2(acc0[p], w0.y, vv.y);                 \
        fma2(acc1[p], w1.x, vv.x); fma2(acc1[p], w1.y, vv.y);                 \
      }                                                                       \
    }                                                                         \
    _Pragma("unroll")                                                         \
    for (int p = 0; p < PPW; p++) {                                           \
      OUT0[p] = unpack_sum(acc0[p]);                                          \
      OUT1[p] = unpack_sum(acc1[p]);                                          \
    }                                                                         \
  }

  for (int cid = blockIdx.x * WPB + warp; cid < nchunks; cid += gwarps) {
    const int base = cid * PPW;

    // ---- per-point coords (lanes 0..7), broadcast via shuffle ----
    int sp_me = 0, b_me = 0;
    if (lane < PPW) {
      int pg = base + lane;
      if (pg >= total_pts) pg = total_pts - 1;
      const int* cc = coords + (size_t)pg * 3;      // coords are int32
      sp_me = cc[0] * I_STRIDE + cc[1] * J_STRIDE + cc[2];
      b_me = pg / N;
    }

    // ---- gather h (before||after) and load x into g ----
#pragma unroll
    for (int p = 0; p < PPW; p++) {
      int sp = __shfl_sync(0xffffffffu, sp_me, p);
      int bb = __shfl_sync(0xffffffffu, b_me, p);
      size_t ofs = (size_t)bb * B_STRIDE + (size_t)lane * C_STRIDE + (unsigned)sp;
      s.h[P0 + p][lane]      = __ldg(before + ofs);
      s.h[P0 + p][lane + 32] = __ldg(after + ofs);
      int pg = base + p; if (pg >= total_pts) pg = total_pts - 1;
      const float* xr = pf + (size_t)pg * 64;
      s.g[P0 + p][lane]      = __ldg(xr + lane);
      s.g[P0 + p][lane + 32] = __ldg(xr + lane + 32);
    }
    __syncwarp();

    // ---- precompute persistent x-projections (g currently holds x) ----
    float zx0[PPW], zx1[PPW], rx0[PPW], rx1[PPW], qx0[PPW], qx1[PPW], dx[PPW], dxd[PPW];
    MV_PASS(Wzx, g, s.bz[lane], s.bz[lane + 32], zx0, zx1);
    MV_PASS(Wrx, g, s.br[lane], s.br[lane + 32], rx0, rx1);
    MV_PASS(Wqx, g, s.bq[lane], s.bq[lane + 32], qx0, qx1);
    MV_PASS(Wd1x, g, s.bd1[lane & 31], 0.0f, dx, dxd);   // only rows 0..31 meaningful
    (void)dxd;
    __syncwarp();   // all lanes done reading x from g before g is reused

    // ---- 4 GRU iterations ----
    float zz0[PPW], zz1[PPW];
#pragma unroll 1
    for (int it = 0; it < 4; it++) {
      // z gate
      {
        unsigned long long acc0[PPW], acc1[PPW];
#pragma unroll
        for (int p = 0; p < PPW; p++) {
          acc0[p] = pack2(zx0[p], 0.0f);
          acc1[p] = pack2(zx1[p], 0.0f);
        }
#pragma unroll 4
        for (int k4 = 0; k4 < 16; k4++) {
          ulonglong2 w0 = ld2(&s.Wzh[lane][k4 * 4]);
          ulonglong2 w1 = ld2(&s.Wzh[lane + 32][k4 * 4]);
#pragma unroll
          for (int p = 0; p < PPW; p++) {
            ulonglong2 hv = ld2(&s.h[P0 + p][k4 * 4]);
            fma2(acc0[p], w0.x, hv.x); fma2(acc0[p], w0.y, hv.y);
            fma2(acc1[p], w1.x, hv.x); fma2(acc1[p], w1.y, hv.y);
          }
        }
#pragma unroll
        for (int p = 0; p < PPW; p++) {
          zz0[p] = fast_sigmoid(unpack_sum(acc0[p]));
          zz1[p] = fast_sigmoid(unpack_sum(acc1[p]));
        }
      }
      // r gate -> g = sigmoid(r)*h
      {
        unsigned long long acc0[PPW], acc1[PPW];
#pragma unroll
        for (int p = 0; p < PPW; p++) {
          acc0[p] = pack2(rx0[p], 0.0f);
          acc1[p] = pack2(rx1[p], 0.0f);
        }
#pragma unroll 4
        for (int k4 = 0; k4 < 16; k4++) {
          ulonglong2 w0 = ld2(&s.Wrh[lane][k4 * 4]);
          ulonglong2 w1 = ld2(&s.Wrh[lane + 32][k4 * 4]);
#pragma unroll
          for (int p = 0; p < PPW; p++) {
            ulonglong2 hv = ld2(&s.h[P0 + p][k4 * 4]);
            fma2(acc0[p], w0.x, hv.x); fma2(acc0[p], w0.y, hv.y);
            fma2(acc1[p], w1.x, hv.x); fma2(acc1[p], w1.y, hv.y);
          }
        }
#pragma unroll
        for (int p = 0; p < PPW; p++) {
          float r0 = fast_sigmoid(unpack_sum(acc0[p]));
          float r1 = fast_sigmoid(unpack_sum(acc1[p]));
          s.g[P0 + p][lane]      = r0 * s.h[P0 + p][lane];
          s.g[P0 + p][lane + 32] = r1 * s.h[P0 + p][lane + 32];
        }
      }
      __syncwarp();
      // q gate + h update
      {
        unsigned long long acc0[PPW], acc1[PPW];
#pragma unroll
        for (int p = 0; p < PPW; p++) {
          acc0[p] = pack2(qx0[p], 0.0f);
          acc1[p] = pack2(qx1[p], 0.0f);
        }
#pragma unroll 4
        for (int k4 = 0; k4 < 16; k4++) {
          ulonglong2 w0 = ld2(&s.Wqh[lane][k4 * 4]);
          ulonglong2 w1 = ld2(&s.Wqh[lane + 32][k4 * 4]);
#pragma unroll
          for (int p = 0; p < PPW; p++) {
            ulonglong2 gv = ld2(&s.g[P0 + p][k4 * 4]);
            fma2(acc0[p], w0.x, gv.x); fma2(acc0[p], w0.y, gv.y);
            fma2(acc1[p], w1.x, gv.x); fma2(acc1[p], w1.y, gv.y);
          }
        }
#pragma unroll
        for (int p = 0; p < PPW; p++) {
          float q0 = fast_tanh(unpack_sum(acc0[p]));
          float q1 = fast_tanh(unpack_sum(acc1[p]));
          float h0 = s.h[P0 + p][lane];
          float h1 = s.h[P0 + p][lane + 32];
          h0 = fmaf(zz0[p], q0 - h0, h0);   // (1-z)h + zq
          h1 = fmaf(zz1[p], q1 - h1, h1);
          s.h[P0 + p][lane]      = h0;
          s.h[P0 + p][lane + 32] = h1;
        }
      }
      __syncwarp();
    }

    // ---- decoder: hmid = gelu(Wd1h@h + d1x) ----
    {
      unsigned long long acc0[PPW];
#pragma unroll
      for (int p = 0; p < PPW; p++) acc0[p] = pack2(dx[p], 0.0f);
#pragma unroll 4
      for (int k4 = 0; k4 < 16; k4++) {
        ulonglong2 w0 = ld2(&s.Wd1h[lane & 31][k4 * 4]);
#pragma unroll
        for (int p = 0; p < PPW; p++) {
          ulonglong2 hv = ld2(&s.h[P0 + p][k4 * 4]);
          fma2(acc0[p], w0.x, hv.x); fma2(acc0[p], w0.y, hv.y);
        }
      }
      if (lane < 32) {
#pragma unroll
        for (int p = 0; p < PPW; p++) {
          float v = unpack_sum(acc0[p]);
          s.g[P0 + p][lane] = 0.5f * v * (1.0f + erff(v * 0.70710678118654752f));
        }
      }
    }
    __syncwarp();

    // ---- flow = Wd2 @ hmid + bd2 (3 outputs) ----
    if (lane < 3) {
#pragma unroll
      for (int p = 0; p < PPW; p++) {
        if (base + p < total_pts) {
          float acc = s.bd2[lane];
#pragma unroll
          for (int m = 0; m < 32; m++)
            acc = fmaf(s.Wd2[lane][m], s.g[P0 + p][m], acc);
          out[(size_t)(base + p) * 3 + lane] = acc;
        }
      }
    }
    __syncwarp();
  }
#undef MV_PASS
}

extern "C" void kernel_launch(void* const* d_in, const int* in_sizes, int n_in,
                              void* d_out, int out_size) {
  const float* before = (const float*)d_in[0];
  const float* after  = (const float*)d_in[1];
  const float* pf     = (const float*)d_in[2];
  const int*   coords = (const int*)d_in[3];     // int32 (JAX x64 disabled)
  const float* Wz  = (const float*)d_in[4];
  const float* bz  = (const float*)d_in[5];
  const float* Wr  = (const float*)d_in[6];
  const float* br  = (const float*)d_in[7];
  const float* Wq  = (const float*)d_in[8];
  const float* bq  = (const float*)d_in[9];
  const float* Wd1 = (const float*)d_in[10];
  const float* bd1 = (const float*)d_in[11];
  const float* Wd2 = (const float*)d_in[12];
  const float* bd2 = (const float*)d_in[13];
  float* out = (float*)d_out;

  int B = in_sizes[0] / (int)(32u * 256u * 256u * 32u);
  if (B < 1) B = 1;
  int total_pts = in_sizes[3] / 3;      // coords has B*N*3 elements
  int N = total_pts / B;

  cudaFuncSetAttribute(gru_decoder_kernel,
                       cudaFuncAttributeMaxDynamicSharedMemorySize,
                       (int)sizeof(Smem));

  gru_decoder_kernel<<<152, NTHREADS, sizeof(Smem)>>>(
      before, after, pf, coords, Wz, bz, Wr, br, Wq, bq,
      Wd1, bd1, Wd2, bd2, out, N, total_pts);
}

// round 6
// speedup vs baseline: 2.8114x; 2.8114x over previous
#include <cuda_runtime.h>
#include <cuda_bf16.h>
#include <math.h>
#include <stdint.h>

#define NTHREADS 256
#define NWARPS 8
#define TILE_M 128

// fixed problem geometry
#define C_STRIDE 2097152ULL     // 256*256*32
#define B_STRIDE 67108864ULL    // 32*256*256*32
#define I_STRIDE 8192
#define J_STRIDE 32

// B-fragment banks: [hi/lo][ (nt*4+kf)*32*2 + lane*2 + w ]
struct __align__(16) Smem {
  unsigned wz_h[2][2048];   // nt 0..7 (n=64), kf 0..3 (k=h 0..63)
  unsigned wr_h[2][2048];
  unsigned wq_h[2][2048];
  unsigned wz_x[2][2048];   // k = x dims (W cols 64..127)
  unsigned wr_x[2][2048];
  unsigned wq_x[2][2048];
  unsigned wd_h[2][1024];   // nt 0..3 (n=32)
  unsigned wd_x[2][1024];
  float xp[NWARPS][28][32][4];   // per-warp xproj dumps: z 0-7, r 8-15, q 16-23, dec 24-27
  float bz[64], br[64], bq[64], bd1[32];
  float Wd2[96], bd2[4];
};

// ---- bf16 pack/unpack helpers ----
__device__ __forceinline__ float bfl(unsigned w) { return __uint_as_float(w << 16); }
__device__ __forceinline__ float bfh(unsigned w) { return __uint_as_float(w & 0xffff0000u); }
__device__ __forceinline__ unsigned packbf(float lo_, float hi_) {
  unsigned r;
  asm("cvt.rn.bf16x2.f32 %0, %1, %2;" : "=r"(r) : "f"(hi_), "f"(lo_));
  return r;
}
// split (v0,v1) -> hi word + lo-residual word
__device__ __forceinline__ void splitp(float v0, float v1, unsigned& hi, unsigned& lo) {
  unsigned h = packbf(v0, v1);
  float r0 = v0 - bfl(h), r1 = v1 - bfh(h);
  hi = h;
  lo = packbf(r0, r1);
}

__device__ __forceinline__ float sigm(float x) {
  return __fdividef(1.0f, 1.0f + __expf(-x));
}
__device__ __forceinline__ float tanhfast(float x) {
  return __fdividef(2.0f, 1.0f + __expf(-2.0f * x)) - 1.0f;
}

// warp HMMA m16n8k16 bf16 -> f32 accumulate
__device__ __forceinline__ void mma4(float d[4], const unsigned a[4], uint2 b) {
  asm volatile(
    "mma.sync.aligned.m16n8k16.row.col.f32.bf16.bf16.f32 "
    "{%0,%1,%2,%3}, {%4,%5,%6,%7}, {%8,%9}, {%0,%1,%2,%3};"
    : "+f"(d[0]), "+f"(d[1]), "+f"(d[2]), "+f"(d[3])
    : "r"(a[0]), "r"(a[1]), "r"(a[2]), "r"(a[3]), "r"(b.x), "r"(b.y));
}

// 12 HMMA: 4 k-frags x 3 split terms, B frags streamed from smem
__device__ __forceinline__ void gemm12(float d[4], const unsigned* whi, const unsigned* wlo,
                                       int nt, int lane,
                                       const unsigned (&AHf)[4][4], const unsigned (&ALf)[4][4]) {
#pragma unroll
  for (int kf = 0; kf < 4; kf++) {
    int o = ((nt * 4 + kf) * 32 + lane) * 2;
    uint2 bh = *(const uint2*)(whi + o);
    uint2 bl = *(const uint2*)(wlo + o);
    mma4(d, AHf[kf], bh);
    mma4(d, ALf[kf], bh);
    mma4(d, AHf[kf], bl);
  }
}

// fill one gate's B-fragment bank (hi+lo) from row-major W[n][128], cols koff..koff+63
__device__ __forceinline__ void fill_frag(unsigned* dst_hi, unsigned* dst_lo,
                                          const float* __restrict__ W, int koff,
                                          int ntn, int tid) {
  int total = ntn * 4 * 32 * 2;
  for (int i = tid; i < total; i += NTHREADS) {
    int w = i & 1;
    int lane = (i >> 1) & 31;
    int kf = (i >> 6) & 3;
    int nt = i >> 8;
    int n = nt * 8 + (lane >> 2);
    int k = kf * 16 + (lane & 3) * 2 + w * 8;
    float v0 = W[n * 128 + koff + k];
    float v1 = W[n * 128 + koff + k + 1];
    unsigned hw, lw;
    splitp(v0, v1, hw, lw);
    dst_hi[i] = hw;
    dst_lo[i] = lw;
  }
}

__global__ __launch_bounds__(NTHREADS, 1)
void gru_hmma_kernel(
    const float* __restrict__ before, const float* __restrict__ after,
    const float* __restrict__ pf, const int* __restrict__ coords,
    const float* __restrict__ Wz, const float* __restrict__ bz,
    const float* __restrict__ Wr, const float* __restrict__ br,
    const float* __restrict__ Wq, const float* __restrict__ bq,
    const float* __restrict__ Wd1, const float* __restrict__ bd1,
    const float* __restrict__ Wd2, const float* __restrict__ bd2,
    float* __restrict__ out, int N, int total_pts)
{
  extern __shared__ char smem_raw[];
  Smem& s = *reinterpret_cast<Smem*>(smem_raw);
  const int tid = threadIdx.x;
  const int wid = tid >> 5, lane = tid & 31;
  const int g = lane >> 2, c2t = (lane & 3) * 2;

  // ---- one-time weight fragment prep ----
  fill_frag(s.wz_h[0], s.wz_h[1], Wz, 0, 8, tid);
  fill_frag(s.wr_h[0], s.wr_h[1], Wr, 0, 8, tid);
  fill_frag(s.wq_h[0], s.wq_h[1], Wq, 0, 8, tid);
  fill_frag(s.wz_x[0], s.wz_x[1], Wz, 64, 8, tid);
  fill_frag(s.wr_x[0], s.wr_x[1], Wr, 64, 8, tid);
  fill_frag(s.wq_x[0], s.wq_x[1], Wq, 64, 8, tid);
  fill_frag(s.wd_h[0], s.wd_h[1], Wd1, 0, 4, tid);
  fill_frag(s.wd_x[0], s.wd_x[1], Wd1, 64, 4, tid);
  if (tid < 64) { s.bz[tid] = bz[tid]; s.br[tid] = br[tid]; s.bq[tid] = bq[tid]; }
  if (tid < 32) s.bd1[tid] = bd1[tid];
  if (tid < 96) s.Wd2[tid] = Wd2[tid];
  if (tid < 3)  s.bd2[tid] = bd2[tid];
  __syncthreads();

  const int ntiles = (total_pts + TILE_M - 1) / TILE_M;

  for (int tile = blockIdx.x; tile < ntiles; tile += gridDim.x) {
    const int ptA = tile * TILE_M + wid * 16 + g;
    const int ptB = ptA + 8;
    const bool vA = ptA < total_pts, vB = ptB < total_pts;
    const int pA = vA ? ptA : total_pts - 1;
    const int pB = vB ? ptB : total_pts - 1;

    // ---- gather h into A fragments (bf16 hi/lo) ----
    unsigned AH[4][4], AL[4][4];
    {
      const int* ccA = coords + (size_t)pA * 3;
      const int* ccB = coords + (size_t)pB * 3;
      int spA = ccA[0] * I_STRIDE + ccA[1] * J_STRIDE + ccA[2];
      int spB = ccB[0] * I_STRIDE + ccB[1] * J_STRIDE + ccB[2];
      const float* befA = before + (size_t)(pA / N) * B_STRIDE + (unsigned)spA;
      const float* aftA = after  + (size_t)(pA / N) * B_STRIDE + (unsigned)spA;
      const float* befB = before + (size_t)(pB / N) * B_STRIDE + (unsigned)spB;
      const float* aftB = after  + (size_t)(pB / N) * B_STRIDE + (unsigned)spB;
#pragma unroll
      for (int kf = 0; kf < 4; kf++) {
        // cols cb,cb+1 (regs 0/1) and cb+8,cb+9 (regs 2/3); kf<2 -> before, else after
        int cb = (kf & 1) * 16 + c2t;   // channel within the 32-ch grid
        const float* pa = (kf < 2) ? befA : aftA;
        const float* pb = (kf < 2) ? befB : aftB;
        float a0 = __ldg(pa + (size_t)cb * C_STRIDE);
        float a1 = __ldg(pa + (size_t)(cb + 1) * C_STRIDE);
        float a2 = __ldg(pa + (size_t)(cb + 8) * C_STRIDE);
        float a3 = __ldg(pa + (size_t)(cb + 9) * C_STRIDE);
        float b0 = __ldg(pb + (size_t)cb * C_STRIDE);
        float b1 = __ldg(pb + (size_t)(cb + 1) * C_STRIDE);
        float b2 = __ldg(pb + (size_t)(cb + 8) * C_STRIDE);
        float b3 = __ldg(pb + (size_t)(cb + 9) * C_STRIDE);
        splitp(a0, a1, AH[kf][0], AL[kf][0]);
        splitp(b0, b1, AH[kf][1], AL[kf][1]);
        splitp(a2, a3, AH[kf][2], AL[kf][2]);
        splitp(b2, b3, AH[kf][3], AL[kf][3]);
      }
    }

    // ---- x A-fragments + x-projection GEMMs -> smem dumps ----
    {
      unsigned XH[4][4], XL[4][4];
      const float2* xA = (const float2*)(pf + (size_t)pA * 64);
      const float2* xB = (const float2*)(pf + (size_t)pB * 64);
#pragma unroll
      for (int kf = 0; kf < 4; kf++) {
        float2 a0 = __ldg(xA + kf * 8 + (lane & 3));
        float2 a2 = __ldg(xA + kf * 8 + (lane & 3) + 4);
        float2 b0 = __ldg(xB + kf * 8 + (lane & 3));
        float2 b2 = __ldg(xB + kf * 8 + (lane & 3) + 4);
        splitp(a0.x, a0.y, XH[kf][0], XL[kf][0]);
        splitp(b0.x, b0.y, XH[kf][1], XL[kf][1]);
        splitp(a2.x, a2.y, XH[kf][2], XL[kf][2]);
        splitp(b2.x, b2.y, XH[kf][3], XL[kf][3]);
      }
      // z, r, q xproj (nt 0..7 each)
#pragma unroll
      for (int nt = 0; nt < 8; nt++) {
        int n0 = nt * 8 + c2t;
        float d[4];
        d[0] = s.bz[n0]; d[1] = s.bz[n0 + 1]; d[2] = d[0]; d[3] = d[1];
        gemm12(d, s.wz_x[0], s.wz_x[1], nt, lane, XH, XL);
        *(float4*)&s.xp[wid][nt][lane][0] = make_float4(d[0], d[1], d[2], d[3]);
      }
#pragma unroll
      for (int nt = 0; nt < 8; nt++) {
        int n0 = nt * 8 + c2t;
        float d[4];
        d[0] = s.br[n0]; d[1] = s.br[n0 + 1]; d[2] = d[0]; d[3] = d[1];
        gemm12(d, s.wr_x[0], s.wr_x[1], nt, lane, XH, XL);
        *(float4*)&s.xp[wid][8 + nt][lane][0] = make_float4(d[0], d[1], d[2], d[3]);
      }
#pragma unroll
      for (int nt = 0; nt < 8; nt++) {
        int n0 = nt * 8 + c2t;
        float d[4];
        d[0] = s.bq[n0]; d[1] = s.bq[n0 + 1]; d[2] = d[0]; d[3] = d[1];
        gemm12(d, s.wq_x[0], s.wq_x[1], nt, lane, XH, XL);
        *(float4*)&s.xp[wid][16 + nt][lane][0] = make_float4(d[0], d[1], d[2], d[3]);
      }
#pragma unroll
      for (int nt = 0; nt < 4; nt++) {
        int n0 = nt * 8 + c2t;
        float d[4];
        d[0] = s.bd1[n0]; d[1] = s.bd1[n0 + 1]; d[2] = d[0]; d[3] = d[1];
        gemm12(d, s.wd_x[0], s.wd_x[1], nt, lane, XH, XL);
        *(float4*)&s.xp[wid][24 + nt][lane][0] = make_float4(d[0], d[1], d[2], d[3]);
      }
    }

    // ---- 4 GRU iterations ----
    float z[8][4];
    unsigned RH[4][4], RL[4][4];
#pragma unroll 1
    for (int it = 0; it < 4; it++) {
      // z gate
#pragma unroll
      for (int nt = 0; nt < 8; nt++) {
        float4 dv = *(const float4*)&s.xp[wid][nt][lane][0];
        float d[4] = {dv.x, dv.y, dv.z, dv.w};
        gemm12(d, s.wz_h[0], s.wz_h[1], nt, lane, AH, AL);
        z[nt][0] = sigm(d[0]); z[nt][1] = sigm(d[1]);
        z[nt][2] = sigm(d[2]); z[nt][3] = sigm(d[3]);
      }
      // r gate -> RH frags (r*h)
#pragma unroll
      for (int nt = 0; nt < 8; nt++) {
        float4 dv = *(const float4*)&s.xp[wid][8 + nt][lane][0];
        float d[4] = {dv.x, dv.y, dv.z, dv.w};
        gemm12(d, s.wr_h[0], s.wr_h[1], nt, lane, AH, AL);
        int kf = nt >> 1, rA = (nt & 1) * 2, rB = rA + 1;
        float hA0 = bfl(AH[kf][rA]) + bfl(AL[kf][rA]);
        float hA1 = bfh(AH[kf][rA]) + bfh(AL[kf][rA]);
        float hB0 = bfl(AH[kf][rB]) + bfl(AL[kf][rB]);
        float hB1 = bfh(AH[kf][rB]) + bfh(AL[kf][rB]);
        float rhA0 = sigm(d[0]) * hA0, rhA1 = sigm(d[1]) * hA1;
        float rhB0 = sigm(d[2]) * hB0, rhB1 = sigm(d[3]) * hB1;
        splitp(rhA0, rhA1, RH[kf][rA], RL[kf][rA]);
        splitp(rhB0, rhB1, RH[kf][rB], RL[kf][rB]);
      }
      // q gate + h update (in place in AH/AL)
#pragma unroll
      for (int nt = 0; nt < 8; nt++) {
        float4 dv = *(const float4*)&s.xp[wid][16 + nt][lane][0];
        float d[4] = {dv.x, dv.y, dv.z, dv.w};
        gemm12(d, s.wq_h[0], s.wq_h[1], nt, lane, RH, RL);
        int kf = nt >> 1, rA = (nt & 1) * 2, rB = rA + 1;
        float hA0 = bfl(AH[kf][rA]) + bfl(AL[kf][rA]);
        float hA1 = bfh(AH[kf][rA]) + bfh(AL[kf][rA]);
        float hB0 = bfl(AH[kf][rB]) + bfl(AL[kf][rB]);
        float hB1 = bfh(AH[kf][rB]) + bfh(AL[kf][rB]);
        float q0 = tanhfast(d[0]), q1 = tanhfast(d[1]);
        float q2 = tanhfast(d[2]), q3 = tanhfast(d[3]);
        hA0 = fmaf(z[nt][0], q0 - hA0, hA0);
        hA1 = fmaf(z[nt][1], q1 - hA1, hA1);
        hB0 = fmaf(z[nt][2], q2 - hB0, hB0);
        hB1 = fmaf(z[nt][3], q3 - hB1, hB1);
        splitp(hA0, hA1, AH[kf][rA], AL[kf][rA]);
        splitp(hB0, hB1, AH[kf][rB], AL[kf][rB]);
      }
    }

    // ---- decoder: hmid = gelu(Wd1h @ h + xproj_dec) ----
    float hm[4][4];
#pragma unroll
    for (int nt = 0; nt < 4; nt++) {
      float4 dv = *(const float4*)&s.xp[wid][24 + nt][lane][0];
      float d[4] = {dv.x, dv.y, dv.z, dv.w};
      gemm12(d, s.wd_h[0], s.wd_h[1], nt, lane, AH, AL);
#pragma unroll
      for (int j = 0; j < 4; j++)
        hm[nt][j] = 0.5f * d[j] * (1.0f + erff(d[j] * 0.70710678118654752f));
    }

    // ---- flow = Wd2 @ hmid + bd2, quad reduction ----
    float fA[3] = {0.f, 0.f, 0.f}, fB[3] = {0.f, 0.f, 0.f};
#pragma unroll
    for (int nt = 0; nt < 4; nt++) {
      int n0 = nt * 8 + c2t;
#pragma unroll
      for (int o = 0; o < 3; o++) {
        float w0 = s.Wd2[o * 32 + n0], w1 = s.Wd2[o * 32 + n0 + 1];
        fA[o] += w0 * hm[nt][0] + w1 * hm[nt][1];
        fB[o] += w0 * hm[nt][2] + w1 * hm[nt][3];
      }
    }
#pragma unroll
    for (int o = 0; o < 3; o++) {
      fA[o] += __shfl_xor_sync(0xffffffffu, fA[o], 1);
      fA[o] += __shfl_xor_sync(0xffffffffu, fA[o], 2);
      fB[o] += __shfl_xor_sync(0xffffffffu, fB[o], 1);
      fB[o] += __shfl_xor_sync(0xffffffffu, fB[o], 2);
    }
    int t = lane & 3;
    if (t < 3) {
      if (vA) out[(size_t)ptA * 3 + t] = fA[t] + s.bd2[t];
      if (vB) out[(size_t)ptB * 3 + t] = fB[t] + s.bd2[t];
    }
  }
}

extern "C" void kernel_launch(void* const* d_in, const int* in_sizes, int n_in,
                              void* d_out, int out_size) {
  const float* before = (const float*)d_in[0];
  const float* after  = (const float*)d_in[1];
  const float* pf     = (const float*)d_in[2];
  const int*   coords = (const int*)d_in[3];     // int32
  const float* Wz  = (const float*)d_in[4];
  const float* bz  = (const float*)d_in[5];
  const float* Wr  = (const float*)d_in[6];
  const float* br  = (const float*)d_in[7];
  const float* Wq  = (const float*)d_in[8];
  const float* bq  = (const float*)d_in[9];
  const float* Wd1 = (const float*)d_in[10];
  const float* bd1 = (const float*)d_in[11];
  const float* Wd2 = (const float*)d_in[12];
  const float* bd2 = (const float*)d_in[13];
  float* out = (float*)d_out;

  int B = in_sizes[0] / (int)(32u * 256u * 256u * 32u);
  if (B < 1) B = 1;
  int total_pts = in_sizes[3] / 3;
  int N = total_pts / B;

  cudaFuncSetAttribute(gru_hmma_kernel,
                       cudaFuncAttributeMaxDynamicSharedMemorySize,
                       (int)sizeof(Smem));

  gru_hmma_kernel<<<152, NTHREADS, sizeof(Smem)>>>(
      before, after, pf, coords, Wz, bz, Wr, br, Wq, bq,
      Wd1, bd1, Wd2, bd2, out, N, total_pts);
}